// round 2
// baseline (speedup 1.0000x reference)
#include <cuda_runtime.h>
#include <math.h>

#define NLEV 16
#define TABLE_SIZE (1u << 19)
#define TMASK (TABLE_SIZE - 1u)
#define PRIME_Y 2654435761u
#define PRIME_Z 805459861u
#define TPB 256

struct ResArr { float r[NLEV]; };

// Process the two x-corners (bl.x, bl.x+1) for one (y,z) hash combo.
// PRIME_X == 1, so when bl.x is even the two corners hash to h and h^1:
// an adjacent float2 pair == one aligned float4 load (half the wavefronts/sectors).
__device__ __forceinline__ void corner_pair(
    const float2* __restrict__ tab2, const float4* __restrict__ tab4,
    bool xeven, unsigned hx0, unsigned hx1, unsigned r,
    float wA, float wB, float& a0, float& a1)
{
    if (xeven) {
        unsigned h = (hx0 ^ r) & TMASK;
        float4 e = __ldg(&tab4[h >> 1]);
        bool odd = (h & 1u) != 0u;
        float e0x = odd ? e.z : e.x;
        float e0y = odd ? e.w : e.y;
        float e1x = odd ? e.x : e.z;
        float e1y = odd ? e.y : e.w;
        a0 += wA * e0x + wB * e1x;
        a1 += wA * e0y + wB * e1y;
    } else {
        unsigned hA = (hx0 ^ r) & TMASK;
        unsigned hB = (hx1 ^ r) & TMASK;
        float2 eA = __ldg(&tab2[hA]);
        float2 eB = __ldg(&tab2[hB]);
        a0 += wA * eA.x + wB * eB.x;
        a1 += wA * eA.y + wB * eB.y;
    }
}

__global__ void __launch_bounds__(TPB)
ingp_hash_kernel(const float* __restrict__ x,
                 const float* __restrict__ emb,
                 float* __restrict__ out,
                 int n, ResArr res)
{
    // Row pitch 33 -> bank (t + k) % 32: conflict-free writes and reads.
    __shared__ float stage[TPB * 33];

    const int tid = threadIdx.x;
    const int pid = blockIdx.x * TPB + tid;

    float x0 = 0.f, x1 = 0.f, x2 = 0.f;
    if (pid < n) {
        x0 = x[3 * pid + 0];
        x1 = x[3 * pid + 1];
        x2 = x[3 * pid + 2];
    }
    // clip to box (IEEE min/max)
    x0 = fminf(fmaxf(x0, -1.f), 1.f);
    x1 = fminf(fmaxf(x1, -1.f), 1.f);
    x2 = fminf(fmaxf(x2, -1.f), 1.f);

#pragma unroll 4
    for (int lvl = 0; lvl < NLEV; ++lvl) {
        const float rf = res.r[lvl];
        const float g = __fdiv_rn(2.0f, rf);          // grid = (BOX_MAX-BOX_MIN)/res

        // bl = floor((x - BOX_MIN)/grid)  -- must be bit-exact vs reference (IEEE div + floor)
        const float t0 = __fdiv_rn(x0 + 1.0f, g);
        const float t1 = __fdiv_rn(x1 + 1.0f, g);
        const float t2 = __fdiv_rn(x2 + 1.0f, g);
        const float f0 = floorf(t0), f1 = floorf(t1), f2 = floorf(t2);
        const int i0 = (int)f0, i1 = (int)f1, i2 = (int)f2;

        // w = (x - (bl*grid + BOX_MIN)) / grid
        const float w0 = __fdiv_rn(x0 - (__fmul_rn(f0, g) - 1.0f), g);
        const float w1 = __fdiv_rn(x1 - (__fmul_rn(f1, g) - 1.0f), g);
        const float w2 = __fdiv_rn(x2 - (__fmul_rn(f2, g) - 1.0f), g);
        const float u0 = 1.0f - w0, u1 = 1.0f - w1, u2 = 1.0f - w2;

        // hash components (uint32 wrap semantics match reference)
        const unsigned hx0 = (unsigned)i0;
        const unsigned hx1 = (unsigned)(i0 + 1);
        const unsigned hy0 = (unsigned)i1 * PRIME_Y;
        const unsigned hy1 = (unsigned)(i1 + 1) * PRIME_Y;
        const unsigned hz0 = (unsigned)i2 * PRIME_Z;
        const unsigned hz1 = (unsigned)(i2 + 1) * PRIME_Z;

        const float2* tab2 = (const float2*)emb + (size_t)lvl * TABLE_SIZE;
        const float4* tab4 = (const float4*)tab2;
        const bool xe = ((i0 & 1) == 0);

        float a0 = 0.f, a1 = 0.f;
        // 4 (y,z) combos x 2 x-corners = 8 corners
        corner_pair(tab2, tab4, xe, hx0, hx1, hy0 ^ hz0, u1 * u2 * u0, u1 * u2 * w0, a0, a1);
        corner_pair(tab2, tab4, xe, hx0, hx1, hy0 ^ hz1, u1 * w2 * u0, u1 * w2 * w0, a0, a1);
        corner_pair(tab2, tab4, xe, hx0, hx1, hy1 ^ hz0, w1 * u2 * u0, w1 * u2 * w0, a0, a1);
        corner_pair(tab2, tab4, xe, hx0, hx1, hy1 ^ hz1, w1 * w2 * u0, w1 * w2 * w0, a0, a1);

        stage[tid * 33 + 2 * lvl + 0] = a0;
        stage[tid * 33 + 2 * lvl + 1] = a1;
    }

    __syncthreads();

    // Coalesced write-out: the block's output region is a contiguous span of
    // TPB*32 floats (row-major [point][32]).
    const long long base = (long long)blockIdx.x * (TPB * 32);
    int lim = (long long)n * 32 - base > (long long)(TPB * 32)
                  ? (TPB * 32)
                  : (int)((long long)n * 32 - base);
    for (int i = tid; i < lim; i += TPB) {
        out[base + i] = stage[(i >> 5) * 33 + (i & 31)];
    }
}

extern "C" void kernel_launch(void* const* d_in, const int* in_sizes, int n_in,
                              void* d_out, int out_size)
{
    const float* x   = (const float*)d_in[0];
    const float* emb = (const float*)d_in[1];
    float* out = (float*)d_out;

    const int n = in_sizes[0] / 3;

    // Resolutions: same double-precision formula as the numpy reference
    // (same glibc libm on the GPU host -> bit-identical floor results).
    ResArr ra;
    {
        const double b = exp((log(512.0) - log(16.0)) / 15.0);
        for (int i = 0; i < NLEV; ++i)
            ra.r[i] = (float)floor(16.0 * pow(b, (double)i));
    }

    const int grid = (n + TPB - 1) / TPB;
    ingp_hash_kernel<<<grid, TPB>>>(x, emb, out, n, ra);
}

// round 3
// speedup vs baseline: 1.9546x; 1.9546x over previous
#include <cuda_runtime.h>
#include <math.h>

#define NLEV 16
#define TABLE_SIZE (1u << 19)
#define TMASK (TABLE_SIZE - 1u)
#define PRIME_Y 2654435761u
#define PRIME_Z 805459861u
#define TPB 256

struct InvArr { float v[NLEV]; };   // res/2 per level

// ---- load phase for one level: computes weights + issues all gathers -------
// PRIME_X == 1: when bl.x is even, corners (bl.x, bl.x+1) hash to h and h^1,
// i.e. an adjacent float2 pair -> one aligned float4 load (half the lines).
// Odd bl.x: two independent float2 loads. The even/odd branch covers ONLY the
// loads; the consume phase is uniform (per-corner swap mask in `meta`).
__device__ __forceinline__ void load_level(
    const float* __restrict__ emb, int lvl, float invg,
    float X0, float X1, float X2,
    float4 e[4], unsigned& meta, float& w0, float& w1, float& w2)
{
    // t = (x - BOX_MIN) * res/2 ; f = floor ; w = frac  (no IEEE divides:
    // trilinear interp is continuous across a floor flip, so the ulp-level
    // deviation from the reference's div-based path is ~3e-5 abs, << 1e-3 tol)
    const float t0 = X0 * invg, t1 = X1 * invg, t2 = X2 * invg;
    const float f0 = floorf(t0), f1 = floorf(t1), f2 = floorf(t2);
    w0 = t0 - f0; w1 = t1 - f1; w2 = t2 - f2;

    const unsigned hx = (unsigned)(int)f0;
    const unsigned hy = (unsigned)(int)f1 * PRIME_Y;
    const unsigned hz = (unsigned)(int)f2 * PRIME_Z;
    // (i+1)*P == i*P + P (mod 2^32)
    const unsigned r0 = hy ^ hz;
    const unsigned r1 = hy ^ (hz + PRIME_Z);
    const unsigned r2 = (hy + PRIME_Y) ^ hz;
    const unsigned r3 = (hy + PRIME_Y) ^ (hz + PRIME_Z);
    const unsigned h0 = (hx ^ r0) & TMASK, h1 = (hx ^ r1) & TMASK;
    const unsigned h2 = (hx ^ r2) & TMASK, h3 = (hx ^ r3) & TMASK;

    const float2* tab2 = (const float2*)emb + (size_t)lvl * TABLE_SIZE;
    const float4* tab4 = (const float4*)tab2;

    if ((hx & 1u) == 0u) {
        e[0] = __ldg(&tab4[h0 >> 1]);
        e[1] = __ldg(&tab4[h1 >> 1]);
        e[2] = __ldg(&tab4[h2 >> 1]);
        e[3] = __ldg(&tab4[h3 >> 1]);
        // if h is odd, corner hx lives in .zw and hx+1 in .xy -> swap at consume
        meta = (h0 & 1u) | ((h1 & 1u) << 1) | ((h2 & 1u) << 2) | ((h3 & 1u) << 3);
    } else {
        const unsigned hx1 = hx + 1u;
        const unsigned g0 = (hx1 ^ r0) & TMASK, g1 = (hx1 ^ r1) & TMASK;
        const unsigned g2 = (hx1 ^ r2) & TMASK, g3 = (hx1 ^ r3) & TMASK;
        float2 a0 = __ldg(&tab2[h0]), b0 = __ldg(&tab2[g0]);
        float2 a1 = __ldg(&tab2[h1]), b1 = __ldg(&tab2[g1]);
        float2 a2 = __ldg(&tab2[h2]), b2 = __ldg(&tab2[g2]);
        float2 a3 = __ldg(&tab2[h3]), b3 = __ldg(&tab2[g3]);
        e[0] = make_float4(a0.x, a0.y, b0.x, b0.y);
        e[1] = make_float4(a1.x, a1.y, b1.x, b1.y);
        e[2] = make_float4(a2.x, a2.y, b2.x, b2.y);
        e[3] = make_float4(a3.x, a3.y, b3.x, b3.y);
        meta = 0u;
    }
}

// ---- uniform consume phase: trilinear accumulate ---------------------------
__device__ __forceinline__ void consume_level(
    const float4 e[4], unsigned meta,
    float w0, float w1, float w2, float& a0, float& a1)
{
    const float u0 = 1.f - w0, u1 = 1.f - w1, u2 = 1.f - w2;
    float c[4];
    c[0] = u1 * u2; c[1] = u1 * w2; c[2] = w1 * u2; c[3] = w1 * w2;
    a0 = 0.f; a1 = 0.f;
#pragma unroll
    for (int k = 0; k < 4; ++k) {
        const bool sw = (meta >> k) & 1u;
        const float ex0 = sw ? e[k].z : e[k].x;
        const float ey0 = sw ? e[k].w : e[k].y;
        const float ex1 = sw ? e[k].x : e[k].z;
        const float ey1 = sw ? e[k].y : e[k].w;
        const float wA = c[k] * u0, wB = c[k] * w0;
        a0 = fmaf(wA, ex0, fmaf(wB, ex1, a0));
        a1 = fmaf(wA, ey0, fmaf(wB, ey1, a1));
    }
}

__global__ void __launch_bounds__(TPB, 3)
ingp_hash_kernel(const float* __restrict__ x,
                 const float* __restrict__ emb,
                 float* __restrict__ out,
                 int n, InvArr inv)
{
    // pitch-33 rows: conflict-free staged writes AND coalesced readback
    __shared__ float stage[TPB * 33];

    const int tid = threadIdx.x;
    const int pid = blockIdx.x * TPB + tid;

    float x0 = 0.f, x1 = 0.f, x2 = 0.f;
    if (pid < n) {
        x0 = x[3 * pid + 0];
        x1 = x[3 * pid + 1];
        x2 = x[3 * pid + 2];
    }
    x0 = fminf(fmaxf(x0, -1.f), 1.f);
    x1 = fminf(fmaxf(x1, -1.f), 1.f);
    x2 = fminf(fmaxf(x2, -1.f), 1.f);
    const float X0 = x0 + 1.f, X1 = x1 + 1.f, X2 = x2 + 1.f;

    // 2-stage software pipeline over levels: level l+1's gathers are in
    // flight while level l is consumed.
    float4 eb[2][4];
    unsigned mb[2];
    float w0b[2], w1b[2], w2b[2];

    load_level(emb, 0, inv.v[0], X0, X1, X2, eb[0], mb[0], w0b[0], w1b[0], w2b[0]);

#pragma unroll
    for (int lvl = 0; lvl < NLEV; ++lvl) {
        const int cur = lvl & 1;
        if (lvl + 1 < NLEV)
            load_level(emb, lvl + 1, inv.v[lvl + 1], X0, X1, X2,
                       eb[cur ^ 1], mb[cur ^ 1],
                       w0b[cur ^ 1], w1b[cur ^ 1], w2b[cur ^ 1]);
        float a0, a1;
        consume_level(eb[cur], mb[cur], w0b[cur], w1b[cur], w2b[cur], a0, a1);
        stage[tid * 33 + 2 * lvl + 0] = a0;
        stage[tid * 33 + 2 * lvl + 1] = a1;
    }

    __syncthreads();

    // Coalesced streaming write-out (don't pollute L2: embeddings live there)
    const long long base = (long long)blockIdx.x * (TPB * 32);
    const long long rem = (long long)n * 32 - base;
    const int lim = rem > (long long)(TPB * 32) ? (TPB * 32) : (int)rem;
    for (int i = tid; i < lim; i += TPB) {
        __stcs(&out[base + i], stage[(i >> 5) * 33 + (i & 31)]);
    }
}

extern "C" void kernel_launch(void* const* d_in, const int* in_sizes, int n_in,
                              void* d_out, int out_size)
{
    const float* x   = (const float*)d_in[0];
    const float* emb = (const float*)d_in[1];
    float* out = (float*)d_out;

    const int n = in_sizes[0] / 3;

    // resolutions via the same double-precision formula as the reference,
    // passed as res/2 (the multiplicative inverse of grid)
    InvArr inv;
    {
        const double b = exp((log(512.0) - log(16.0)) / 15.0);
        for (int i = 0; i < NLEV; ++i)
            inv.v[i] = (float)(floor(16.0 * pow(b, (double)i)) * 0.5);
    }

    const int grid = (n + TPB - 1) / TPB;
    ingp_hash_kernel<<<grid, TPB>>>(x, emb, out, n, inv);
}